// round 17
// baseline (speedup 1.0000x reference)
#include <cuda_runtime.h>
#include <cuda_bf16.h>
#include <math_constants.h>
#include <cstdint>

// Problem constants
#define BATCH 8
#define TSEQ  2048
#define NHEAD 6
#define HDIM  64
#define CDIM  (NHEAD * HDIM)      // 384
#define C3    (3 * CDIM)          // 1152
#define MROWS (BATCH * TSEQ)      // 16384

#define SCALE_LOG2E 0.18033688011112042f   // (1/8) * log2(e), folded into q

// Scratch (device globals; no runtime allocation allowed)
__device__ float g_q[BATCH * NHEAD * TSEQ * HDIM];   // [B,H,T,D] tf32, pre-scaled
__device__ float g_k[BATCH * NHEAD * TSEQ * HDIM];
__device__ float g_v[BATCH * NHEAD * TSEQ * HDIM];
__device__ float g_att[MROWS * CDIM];                // [B,T,C] tf32-rounded

// ---------------------------------------------------------------------------
// Helpers
// ---------------------------------------------------------------------------
__device__ __forceinline__ unsigned f2tf32(float f) {
    unsigned u;
    asm("cvt.rna.tf32.f32 %0, %1;" : "=r"(u) : "f"(f));
    return u;
}
__device__ __forceinline__ float rtf(float f) { return __uint_as_float(f2tf32(f)); }
__device__ __forceinline__ float fast_exp2(float x) {
    float y;
    asm("ex2.approx.f32 %0, %1;" : "=f"(y) : "f"(x));
    return y;
}
__device__ __forceinline__ void mma_tf32(float* d, const unsigned* a, unsigned b0, unsigned b1) {
    asm volatile(
        "mma.sync.aligned.m16n8k8.row.col.f32.tf32.tf32.f32 "
        "{%0,%1,%2,%3},{%4,%5,%6,%7},{%8,%9},{%0,%1,%2,%3};"
        : "+f"(d[0]), "+f"(d[1]), "+f"(d[2]), "+f"(d[3])
        : "r"(a[0]), "r"(a[1]), "r"(a[2]), "r"(a[3]), "r"(b0), "r"(b1));
}
__device__ __forceinline__ unsigned smaddr(const void* p) {
    return (unsigned)__cvta_generic_to_shared(p);
}
__device__ __forceinline__ void cp16(unsigned dst, const void* src) {
    asm volatile("cp.async.cg.shared.global [%0], [%1], 16;" :: "r"(dst), "l"(src));
}

// ---------------------------------------------------------------------------
// Hybrid TF32 GEMM (round-16, plus row offset for batch-split launches)
// ---------------------------------------------------------------------------
#define LDP 136
#define APITCH_F 20      // floats per A row (80 bytes)

template<int NC, bool PROJ, int TPB, int BM>
__global__ __launch_bounds__(TPB, 2) void gemm_tf32_kernel(
    const float* __restrict__ Ain, const float* __restrict__ W,
    const float* __restrict__ bias, float* __restrict__ out, int m_off)
{
    __shared__ float Abuf[2][BM * APITCH_F];
    __shared__ float Bsh[2][16][LDP];

    const float* A = PROJ ? (const float*)g_att : Ain;

    const int tid  = threadIdx.x;
    const int lane = tid & 31, warp = tid >> 5;
    const int wm = warp >> 1, wn = warp & 1;
    const int gid = lane >> 2, tig = lane & 3;
    const int bm = m_off + blockIdx.y * BM, bn = blockIdx.x * 128;

    constexpr int IB = 256 / TPB;
    constexpr int IA = BM * 4 / TPB;

    float acc[2][8][4];
    #pragma unroll
    for (int mi = 0; mi < 2; mi++)
        #pragma unroll
        for (int ni = 0; ni < 8; ni++)
            #pragma unroll
            for (int c = 0; c < 4; c++) acc[mi][ni][c] = 0.f;

    float4 vbr[IB][2];

#define LOAD_W(c)  do { \
        _Pragma("unroll") \
        for (int i = 0; i < IB; i++) { \
            const int idx = i * TPB + tid; \
            const int br = idx >> 4, bc = (idx & 15) * 8; \
            const float* wp = W + (size_t)((c) * 16 + br) * NC + bn + bc; \
            vbr[i][0] = *(const float4*)(wp); \
            vbr[i][1] = *(const float4*)(wp + 4); \
        } \
    } while (0)

#define STAGE_B(BUF)  do { \
        _Pragma("unroll") \
        for (int i = 0; i < IB; i++) { \
            const int idx = i * TPB + tid; \
            const int br = idx >> 4, bc = (idx & 15) * 8; \
            float4 q0 = vbr[i][0], q1 = vbr[i][1]; \
            *(float4*)&Bsh[BUF][br][bc]     = make_float4(rtf(q0.x), rtf(q0.y), rtf(q0.z), rtf(q0.w)); \
            *(float4*)&Bsh[BUF][br][bc + 4] = make_float4(rtf(q1.x), rtf(q1.y), rtf(q1.z), rtf(q1.w)); \
        } \
    } while (0)

#define STAGE_A(c, BUF)  do { \
        _Pragma("unroll") \
        for (int i = 0; i < IA; i++) { \
            const int idx = i * TPB + tid; \
            const int row = idx >> 2, g = idx & 3; \
            cp16(smaddr((char*)&Abuf[BUF][0] + row * 80 + g * 16), \
                 A + (size_t)(bm + row) * CDIM + (c) * 16 + g * 4); \
        } \
        asm volatile("cp.async.commit_group;"); \
    } while (0)

    STAGE_A(0, 0);
    LOAD_W(0);
    STAGE_B(0);
    LOAD_W(1);
    asm volatile("cp.async.wait_group 0;");
    __syncthreads();

    #pragma unroll 1
    for (int c = 0; c < 24; c++) {
        const int cur = c & 1;
        if (c < 23) {
            STAGE_B(cur ^ 1);
            STAGE_A(c + 1, cur ^ 1);
        }
        if (c < 22) LOAD_W(c + 2);

        const float* Ab = &Abuf[cur][0];
        #pragma unroll
        for (int ks = 0; ks < 2; ks++) {
            const int k0i = ks * 8 + tig;
            const int k1i = k0i + 4;

            unsigned a[2][4];
            #pragma unroll
            for (int mi = 0; mi < 2; mi++) {
                const int m = wm * 32 + mi * 16 + gid;
                if (PROJ) {
                    a[mi][0] = __float_as_uint(Ab[m * APITCH_F + k0i]);
                    a[mi][1] = __float_as_uint(Ab[(m + 8) * APITCH_F + k0i]);
                    a[mi][2] = __float_as_uint(Ab[m * APITCH_F + k1i]);
                    a[mi][3] = __float_as_uint(Ab[(m + 8) * APITCH_F + k1i]);
                } else {
                    a[mi][0] = f2tf32(Ab[m * APITCH_F + k0i]);
                    a[mi][1] = f2tf32(Ab[(m + 8) * APITCH_F + k0i]);
                    a[mi][2] = f2tf32(Ab[m * APITCH_F + k1i]);
                    a[mi][3] = f2tf32(Ab[(m + 8) * APITCH_F + k1i]);
                }
            }
            #pragma unroll
            for (int ni = 0; ni < 8; ni++) {
                const int n = wn * 64 + ni * 8 + gid;
                unsigned b0 = __float_as_uint(Bsh[cur][k0i][n]);
                unsigned b1 = __float_as_uint(Bsh[cur][k1i][n]);
                mma_tf32(acc[0][ni], a[0], b0, b1);
                mma_tf32(acc[1][ni], a[1], b0, b1);
            }
        }
        asm volatile("cp.async.wait_group 0;");
        __syncthreads();
    }

#undef LOAD_W
#undef STAGE_B
#undef STAGE_A

    #pragma unroll
    for (int mi = 0; mi < 2; mi++) {
        const int r0 = bm + wm * 32 + mi * 16 + gid;
        const int r1 = r0 + 8;
        #pragma unroll
        for (int ni = 0; ni < 8; ni++) {
            if (PROJ) {
                const int c = bn + wn * 64 + ni * 8 + tig * 2;
                float bx = bias[c], by = bias[c + 1];
                *(float2*)(out + (size_t)r0 * CDIM + c) =
                    make_float2(acc[mi][ni][0] + bx, acc[mi][ni][1] + by);
                *(float2*)(out + (size_t)r1 * CDIM + c) =
                    make_float2(acc[mi][ni][2] + bx, acc[mi][ni][3] + by);
            } else {
                const int which = bn / CDIM;                       // 0=q,1=k,2=v
                const int cloc  = (bn % CDIM) + wn * 64 + ni * 8 + tig * 2;
                const int h = cloc >> 6, dd = cloc & 63;
                float* dst = (which == 0) ? g_q : (which == 1) ? g_k : g_v;
                const float sc = (which == 0) ? SCALE_LOG2E : 1.0f;
                const int b0r = r0 >> 11, t0 = r0 & 2047;
                const int b1r = r1 >> 11, t1 = r1 & 2047;
                float2 v0 = make_float2(rtf(acc[mi][ni][0] * sc), rtf(acc[mi][ni][1] * sc));
                float2 v1 = make_float2(rtf(acc[mi][ni][2] * sc), rtf(acc[mi][ni][3] * sc));
                *(float2*)(dst + (((size_t)(b0r * NHEAD + h) * TSEQ + t0) << 6) + dd) = v0;
                *(float2*)(dst + (((size_t)(b1r * NHEAD + h) * TSEQ + t1) << 6) + dd) = v1;
            }
        }
    }
}

// ---------------------------------------------------------------------------
// Causal flash attention (FROZEN round-8 structure) + bh offset for splits.
// ---------------------------------------------------------------------------
__device__ __forceinline__ int sw(int row, int col) {
    return row * 64 + (((((unsigned)col >> 2) ^ (row & 7)) << 2) | (col & 3));
}

__global__ __launch_bounds__(256, 2) void flash_attn_kernel(int bh_off)
{
    extern __shared__ float smf[];
    float* Kbuf = smf;             // [2][4096]
    float* Vbuf = smf + 8192;      // [2][4096]
    float* Ps   = smf + 16384;     // [128][64] swizzled (Q staging, then P)

    const int bh   = bh_off + blockIdx.y;
    const int qb   = 15 - blockIdx.x;      // heavy q-blocks first
    const int tid  = threadIdx.x;
    const int lane = tid & 31;
    const int warp = tid >> 5;
    const int gid  = lane >> 2;
    const int tig  = lane & 3;

    const float* __restrict__ Qb = g_q + (size_t)bh * TSEQ * HDIM;
    const float* __restrict__ Kb = g_k + (size_t)bh * TSEQ * HDIM;
    const float* __restrict__ Vb = g_v + (size_t)bh * TSEQ * HDIM;

    const int qrow0 = warp * 16 + gid;
    const int qrow1 = qrow0 + 8;
    const int qg0   = qb * 128 + qrow0;
    const int qg1   = qb * 128 + qrow1;

    {
        const float4* Qg = (const float4*)(Qb + (size_t)qb * 128 * HDIM);
        float4* P4 = (float4*)Ps;
        #pragma unroll
        for (int i = 0; i < 8; i++) {
            int idx = i * 256 + tid;
            int row = idx >> 4, c4 = idx & 15;
            P4[row * 16 + (c4 ^ (row & 7))] = Qg[idx];
        }
    }

    {
        const float4* Kg = (const float4*)Kb;
        const float4* Vg = (const float4*)Vb;
        #pragma unroll
        for (int i = 0; i < 4; i++) {
            int idx = i * 256 + tid;
            int row = idx >> 4, c4 = idx & 15;
            int s4 = row * 16 + (c4 ^ (row & 7));
            cp16(smaddr(Kbuf + s4 * 4), Kg + idx);
            cp16(smaddr(Vbuf + s4 * 4), Vg + idx);
        }
        asm volatile("cp.async.commit_group;");
    }
    __syncthreads();

    unsigned qa[8][4];
    #pragma unroll
    for (int kc = 0; kc < 8; kc++) {
        int col = kc * 8 + tig;
        qa[kc][0] = __float_as_uint(Ps[sw(qrow0, col)]);
        qa[kc][1] = __float_as_uint(Ps[sw(qrow1, col)]);
        qa[kc][2] = __float_as_uint(Ps[sw(qrow0, col + 4)]);
        qa[kc][3] = __float_as_uint(Ps[sw(qrow1, col + 4)]);
    }

    const int jtmax  = 2 * qb + 1;
    const int mydiag = 2 * qb + (warp >> 2);

    float o[8][4];
    #pragma unroll
    for (int n = 0; n < 8; n++)
        #pragma unroll
        for (int c = 0; c < 4; c++) o[n][c] = 0.f;
    float m0 = -1e30f, m1 = -1e30f, l0 = 0.f, l1 = 0.f;

    #pragma unroll 1
    for (int jt = 0; jt <= jtmax; jt++) {
        const int cur = jt & 1;

        asm volatile("cp.async.wait_group 0;");
        __syncthreads();

        if (jt < jtmax) {
            const float4* Kg = (const float4*)(Kb + (size_t)(jt + 1) * 64 * HDIM);
            const float4* Vg = (const float4*)(Vb + (size_t)(jt + 1) * 64 * HDIM);
            float* Kd = Kbuf + (cur ^ 1) * 4096;
            float* Vd = Vbuf + (cur ^ 1) * 4096;
            #pragma unroll
            for (int i = 0; i < 4; i++) {
                int idx = i * 256 + tid;
                int row = idx >> 4, c4 = idx & 15;
                int s4 = row * 16 + (c4 ^ (row & 7));
                cp16(smaddr(Kd + s4 * 4), Kg + idx);
                cp16(smaddr(Vd + s4 * 4), Vg + idx);
            }
            asm volatile("cp.async.commit_group;");
        }

        if (jt <= mydiag) {
            const float* Ks = Kbuf + cur * 4096;
            const float* Vs = Vbuf + cur * 4096;

            float s[8][4];
            #pragma unroll
            for (int n = 0; n < 8; n++) {
                s[n][0] = s[n][1] = s[n][2] = s[n][3] = 0.f;
                #pragma unroll
                for (int kc = 0; kc < 8; kc++) {
                    unsigned b0 = __float_as_uint(Ks[sw(n * 8 + gid, kc * 8 + tig)]);
                    unsigned b1 = __float_as_uint(Ks[sw(n * 8 + gid, kc * 8 + tig + 4)]);
                    mma_tf32(s[n], qa[kc], b0, b1);
                }
            }

            if (jt == mydiag) {
                const int jbase = jt * 64;
                #pragma unroll
                for (int n = 0; n < 8; n++) {
                    int j0 = jbase + n * 8 + 2 * tig;
                    if (j0 > qg0)     s[n][0] = -1e30f;
                    if (j0 + 1 > qg0) s[n][1] = -1e30f;
                    if (j0 > qg1)     s[n][2] = -1e30f;
                    if (j0 + 1 > qg1) s[n][3] = -1e30f;
                }
            }

            float mx0 = -1e30f, mx1 = -1e30f;
            #pragma unroll
            for (int n = 0; n < 8; n++) {
                mx0 = fmaxf(mx0, fmaxf(s[n][0], s[n][1]));
                mx1 = fmaxf(mx1, fmaxf(s[n][2], s[n][3]));
            }
            mx0 = fmaxf(mx0, __shfl_xor_sync(0xffffffffu, mx0, 1));
            mx0 = fmaxf(mx0, __shfl_xor_sync(0xffffffffu, mx0, 2));
            mx1 = fmaxf(mx1, __shfl_xor_sync(0xffffffffu, mx1, 1));
            mx1 = fmaxf(mx1, __shfl_xor_sync(0xffffffffu, mx1, 2));

            const float mn0 = fmaxf(m0, mx0);
            const float mn1 = fmaxf(m1, mx1);
            const float cr0 = fast_exp2(m0 - mn0);
            const float cr1 = fast_exp2(m1 - mn1);
            m0 = mn0; m1 = mn1;
            l0 *= cr0; l1 *= cr1;
            #pragma unroll
            for (int n = 0; n < 8; n++) {
                o[n][0] *= cr0; o[n][1] *= cr0;
                o[n][2] *= cr1; o[n][3] *= cr1;
            }

            float sum0 = 0.f, sum1 = 0.f;
            #pragma unroll
            for (int n = 0; n < 8; n++) {
                float p00 = fast_exp2(s[n][0] - mn0);
                float p01 = fast_exp2(s[n][1] - mn0);
                float p10 = fast_exp2(s[n][2] - mn1);
                float p11 = fast_exp2(s[n][3] - mn1);
                sum0 += p00 + p01;
                sum1 += p10 + p11;
                int col = n * 8 + 2 * tig;
                *(float2*)&Ps[sw(qrow0, col)] = make_float2(p00, p01);
                *(float2*)&Ps[sw(qrow1, col)] = make_float2(p10, p11);
            }
            sum0 += __shfl_xor_sync(0xffffffffu, sum0, 1);
            sum0 += __shfl_xor_sync(0xffffffffu, sum0, 2);
            sum1 += __shfl_xor_sync(0xffffffffu, sum1, 1);
            sum1 += __shfl_xor_sync(0xffffffffu, sum1, 2);
            l0 += sum0; l1 += sum1;

            __syncwarp();

            #pragma unroll
            for (int kc = 0; kc < 8; kc++) {
                unsigned pa[4];
                int col = kc * 8 + tig;
                pa[0] = f2tf32(Ps[sw(qrow0, col)]);
                pa[1] = f2tf32(Ps[sw(qrow1, col)]);
                pa[2] = f2tf32(Ps[sw(qrow0, col + 4)]);
                pa[3] = f2tf32(Ps[sw(qrow1, col + 4)]);
                #pragma unroll
                for (int dn = 0; dn < 8; dn++) {
                    unsigned b0 = __float_as_uint(Vs[sw(kc * 8 + tig,     dn * 8 + gid)]);
                    unsigned b1 = __float_as_uint(Vs[sw(kc * 8 + tig + 4, dn * 8 + gid)]);
                    mma_tf32(o[dn], pa, b0, b1);
                }
            }
        }
    }

    const float inv0 = 1.f / l0;
    const float inv1 = 1.f / l1;
    const int b = bh / NHEAD, h = bh % NHEAD;
    float* base0 = g_att + (size_t)(b * TSEQ + qg0) * CDIM + h * HDIM;
    float* base1 = g_att + (size_t)(b * TSEQ + qg1) * CDIM + h * HDIM;
    #pragma unroll
    for (int dn = 0; dn < 8; dn++) {
        int col = dn * 8 + 2 * tig;
        *(float2*)(base0 + col) = make_float2(rtf(o[dn][0] * inv0), rtf(o[dn][1] * inv0));
        *(float2*)(base1 + col) = make_float2(rtf(o[dn][2] * inv1), rtf(o[dn][3] * inv1));
    }
}

// ---------------------------------------------------------------------------
// Launcher: batch-split fork/join pipeline.
//   s0: qkv_A | qkv_B | (wait fA) proj_A | (wait fB) proj_B
//   s1: (wait eA) flash_A | (wait eB) flash_B
// Events create graph edges under capture; no sync, no device allocation.
// ---------------------------------------------------------------------------
#define HROWS (MROWS / 2)   // 8192 rows = batches 0-3

extern "C" void kernel_launch(void* const* d_in, const int* in_sizes, int n_in,
                              void* d_out, int out_size)
{
    const float* x      = (const float*)d_in[0];   // [8,2048,384]
    const float* w_qkv  = (const float*)d_in[1];   // [384,1152]
    const float* w_proj = (const float*)d_in[2];   // [384,384]
    const float* b_proj = (const float*)d_in[3];   // [384]
    float* out = (float*)d_out;                    // [8,2048,384]

    cudaFuncSetAttribute(flash_attn_kernel,
                         cudaFuncAttributeMaxDynamicSharedMemorySize, 98304);

    cudaStream_t s1;
    cudaStreamCreateWithFlags(&s1, cudaStreamNonBlocking);
    cudaEvent_t eA, eB, fA, fB;
    cudaEventCreateWithFlags(&eA, cudaEventDisableTiming);
    cudaEventCreateWithFlags(&eB, cudaEventDisableTiming);
    cudaEventCreateWithFlags(&fA, cudaEventDisableTiming);
    cudaEventCreateWithFlags(&fB, cudaEventDisableTiming);

    const dim3 gq(C3 / 128, HROWS / 128);          // (9, 64) per half
    const dim3 gf(TSEQ / 128, BATCH * NHEAD / 2);  // (16, 24) per half
    const dim3 gp(CDIM / 128, HROWS / 64);         // (3, 128) per half

    // stream 0: qkv halves
    gemm_tf32_kernel<C3, false, 256, 128><<<gq, 256>>>(x, w_qkv, nullptr, nullptr, 0);
    cudaEventRecord(eA, 0);
    gemm_tf32_kernel<C3, false, 256, 128><<<gq, 256>>>(x, w_qkv, nullptr, nullptr, HROWS);
    cudaEventRecord(eB, 0);

    // stream 1: flash halves
    cudaStreamWaitEvent(s1, eA, 0);
    flash_attn_kernel<<<gf, 256, 98304, s1>>>(0);
    cudaEventRecord(fA, s1);
    cudaStreamWaitEvent(s1, eB, 0);
    flash_attn_kernel<<<gf, 256, 98304, s1>>>(BATCH * NHEAD / 2);
    cudaEventRecord(fB, s1);

    // stream 0: proj halves (proj_A overlaps flash_B)
    cudaStreamWaitEvent(0, fA, 0);
    gemm_tf32_kernel<CDIM, true, 128, 64><<<gp, 128>>>(nullptr, w_proj, b_proj, out, 0);
    cudaStreamWaitEvent(0, fB, 0);
    gemm_tf32_kernel<CDIM, true, 128, 64><<<gp, 128>>>(nullptr, w_proj, b_proj, out, HROWS);
}